// round 15
// baseline (speedup 1.0000x reference)
#include <cuda_runtime.h>
#include <cuda_bf16.h>
#include <math.h>
#include <stdint.h>

// pre-converted bf16 weights in smem-ready layouts (written by prep_kernel each launch)
static __device__ __align__(16) __nv_bfloat16 g_wqkv[3 * 96 * 104];  // [h][n][k], stride 104
static __device__ __align__(16) __nv_bfloat16 g_wproj[96 * 104];     // [n][k]
static __device__ __align__(16) __nv_bfloat16 g_w1[12 * 32 * 104];   // [nc][n][k]
static __device__ __align__(16) __nv_bfloat16 g_w2[12 * 96 * 40];    // [nc][n][k]

__global__ void prep_kernel(
    const float* __restrict__ qkvw, const float* __restrict__ pw,
    const float* __restrict__ w1,   const float* __restrict__ w2)
{
    const int stride = gridDim.x * blockDim.x;
    const int tid0 = blockIdx.x * blockDim.x + threadIdx.x;
    for (int i = tid0; i < 3 * 96 * 96; i += stride) {
        int h = i / 9216, r = i - h * 9216, n = r / 96, k = r - n * 96;
        int sec = n >> 5, d = n & 31;
        g_wqkv[h * 9984 + n * 104 + k] = __float2bfloat16(qkvw[k * 288 + sec * 96 + h * 32 + d]);
    }
    for (int i = tid0; i < 96 * 96; i += stride) {
        int n = i / 96, k = i - n * 96;
        g_wproj[n * 104 + k] = __float2bfloat16(pw[k * 96 + n]);
    }
    for (int i = tid0; i < 96 * 384; i += stride) {
        int k = i / 384, c = i - k * 384;
        int nc = c >> 5, n = c & 31;
        g_w1[nc * 3328 + n * 104 + k] = __float2bfloat16(w1[i]);
    }
    for (int i = tid0; i < 384 * 96; i += stride) {
        int kr = i / 96, n = i - kr * 96;
        int nc = kr >> 5, kk = kr & 31;
        g_w2[nc * 3840 + n * 40 + kk] = __float2bfloat16(w2[i]);
    }
}

// ===================== mma / ldmatrix / cp.async helpers =====================
__device__ __forceinline__ void mma_bf16(float d[4],
    uint32_t a0, uint32_t a1, uint32_t a2, uint32_t a3, uint32_t b0, uint32_t b1)
{
    asm volatile(
        "mma.sync.aligned.m16n8k16.row.col.f32.bf16.bf16.f32 "
        "{%0,%1,%2,%3},{%4,%5,%6,%7},{%8,%9},{%0,%1,%2,%3};"
        : "+f"(d[0]), "+f"(d[1]), "+f"(d[2]), "+f"(d[3])
        : "r"(a0), "r"(a1), "r"(a2), "r"(a3), "r"(b0), "r"(b1));
}
__device__ __forceinline__ void ldm_x4(uint32_t& r0, uint32_t& r1, uint32_t& r2, uint32_t& r3,
                                       uint32_t addr)
{
    asm volatile("ldmatrix.sync.aligned.m8n8.x4.shared.b16 {%0,%1,%2,%3}, [%4];"
                 : "=r"(r0), "=r"(r1), "=r"(r2), "=r"(r3) : "r"(addr));
}
__device__ __forceinline__ uint32_t pack_bf16(float lo, float hi) {
    uint32_t r;
    asm("cvt.rn.bf16x2.f32 %0, %1, %2;" : "=r"(r) : "f"(hi), "f"(lo)); // d.hi=%1, d.lo=%2
    return r;
}
__device__ __forceinline__ float gelu_fast(float v) {
    float u = v * (0.79788456f + 0.035677408f * v * v);
    float th; asm("tanh.approx.f32 %0, %1;" : "=f"(th) : "f"(u));
    return 0.5f * v * (1.f + th);
}
__device__ __forceinline__ void cp16(uint32_t dst, const void* src) {
    asm volatile("cp.async.cg.shared.global [%0], [%1], 16;" :: "r"(dst), "l"(src) : "memory");
}
#define CP_COMMIT() asm volatile("cp.async.commit_group;" ::: "memory")
#define CP_WAIT0()  asm volatile("cp.async.wait_group 0;" ::: "memory")
#define CP_WAIT1()  asm volatile("cp.async.wait_group 1;" ::: "memory")
#define WIN_BAR(id) asm volatile("bar.sync %0, 128;" :: "r"(id) : "memory")

// ---------------- fused kernel smem layout (bytes) ----------------
// Phase A:
constexpr uint32_t AB_SA  = 0;        // 128 x 104 bf16 LN1 tokens      (26624)
constexpr uint32_t AB_SW0 = 26624;    // weight buf 0: 96 x 104 bf16    (19968)
constexpr uint32_t AB_SW1 = 46592;    // weight buf 1                   (19968) -> 66560
constexpr uint32_t AB_SK  = 66560;    // 128 x 40 bf16                  (10240) -> 76800
constexpr uint32_t AB_SVT = 76800;    // 32 x 136 bf16                  (8704)  -> 85504
constexpr uint32_t AB_RPB = 85504;    // 675 f32                        -> 88208 (pad)
constexpr uint32_t AB_REG = 88208;    // 128 int                        -> 88720
constexpr uint32_t AB_BQ  = 88720;    // 288 f32 qkv bias (per-head)    -> 89872
// Phase B (overlays phase A up to 109440):
constexpr uint32_t PB_X1  = 0;        // x1 f32 128 x stride 98         (50176)
constexpr uint32_t PB_W1  = 50176;    // 4 x (32 x 104 bf16 = 6656)     -> 76800
constexpr uint32_t PB_W2  = 76800;    // 4 x (96 x 40 bf16 = 7680)      -> 107520
constexpr uint32_t PB_B1  = 107520;   // 384 f32 fc1 bias               -> 109056
constexpr uint32_t PB_B2  = 109056;   // 96 f32 fc2 bias                -> 109440
// Persistent (never overlaid):
constexpr uint32_t PS_SRC = 109440;   // 128 int                        -> 109952
constexpr uint32_t PS_BP  = 109952;   // 96 f32 proj bias               -> 110336
constexpr uint32_t PS_N2W = 110336;   // 96 f32                         -> 110720
constexpr uint32_t PS_N2B = 110720;   // 96 f32                         -> 111104
constexpr uint32_t SM_BYTES = 111104;

__global__ __launch_bounds__(256, 2) void block_kernel(
    const float* __restrict__ x,
    const float* __restrict__ n1w, const float* __restrict__ n1b,
    const float* __restrict__ qkvb,
    const float* __restrict__ rpb,
    const float* __restrict__ pb,
    const float* __restrict__ n2w, const float* __restrict__ n2b,
    const float* __restrict__ b1,  const float* __restrict__ b2,
    float* __restrict__ out)
{
    extern __shared__ char smc[];
    __nv_bfloat16* sA  = (__nv_bfloat16*)(smc + AB_SA);
    __nv_bfloat16* sK  = (__nv_bfloat16*)(smc + AB_SK);
    __nv_bfloat16* sVt = (__nv_bfloat16*)(smc + AB_SVT);
    float* sRPB = (float*)(smc + AB_RPB);
    int*   sReg = (int*)(smc + AB_REG);
    int*   sSrc = (int*)(smc + PS_SRC);
    float* sBQ  = (float*)(smc + AB_BQ);
    float* sBP  = (float*)(smc + PS_BP);
    float* sN2W = (float*)(smc + PS_N2W);
    float* sN2B = (float*)(smc + PS_N2B);
    float* sX1  = (float*)(smc + PB_X1);
    float* sB1  = (float*)(smc + PB_B1);
    float* sB2  = (float*)(smc + PB_B2);

    const uint32_t smem_u = (uint32_t)__cvta_generic_to_shared(smc);

    const int tid  = threadIdx.x;
    const int w    = tid >> 5;
    const int lane = tid & 31;
    const int g    = lane >> 2;
    const int t    = lane & 3;
    const int rowA = w * 16 + g;

    // ldmatrix per-lane tile coords
    const int quad = lane >> 3, qr = lane & 7;
    const int arow = (quad & 1) * 8 + qr;
    const int acol = (quad >> 1) * 8;
    const int brow = (quad >> 1) * 8 + qr;
    const int bcol = (quad & 1) * 8;

    const int bw  = blockIdx.x;
    const int bb  = bw >> 7;
    const int wh  = (bw >> 3) & 15;
    const int wwp = bw & 7;
    const float scale = 0.17677669529663687f;

    // kick off head-0 weight staging immediately
    for (int i = tid; i < 1248; i += 256)
        cp16(smem_u + AB_SW0 + i * 16, (const char*)g_wqkv + i * 16);
    CP_COMMIT();

    // metadata + bias staging
    if (tid < 128) {
        int win0 = tid >> 6, tok = tid & 63;
        int i = tok >> 3, j = tok & 7;
        int hr = wh * 8 + i, wr = (wwp * 2 + win0) * 8 + j;
        int hs = (hr + 4) & 127, ws = (wr + 4) & 127;
        sSrc[tid] = bb * 16384 + hs * 128 + ws;
        int rh = hr < 120 ? 0 : (hr < 124 ? 1 : 2);
        int rw = wr < 120 ? 0 : (wr < 124 ? 1 : 2);
        sReg[tid] = rh * 3 + rw;
    }
    for (int q = tid; q < 675; q += 256) sRPB[q] = rpb[q];
    for (int i = tid; i < 288; i += 256) {
        int h = i / 96, n = i - h * 96;
        sBQ[i] = qkvb[(n >> 5) * 96 + h * 32 + (n & 31)];
    }
    if (tid < 96) { sBP[tid] = pb[tid]; sN2W[tid] = n2w[tid]; sN2B[tid] = n2b[tid]; }
    __syncthreads();

    // gather + LN1 -> sA bf16 (own-warp rows)
    {
        float wv0 = n1w[lane], wv1 = n1w[lane + 32], wv2 = n1w[lane + 64];
        float bv0 = n1b[lane], bv1 = n1b[lane + 32], bv2 = n1b[lane + 64];
        for (int rr = 0; rr < 16; ++rr) {
            int n = w * 16 + rr;
            const float* px = x + (size_t)sSrc[n] * 96;
            float v0 = px[lane], v1 = px[lane + 32], v2 = px[lane + 64];
            float s = v0 + v1 + v2, s2 = v0 * v0 + v1 * v1 + v2 * v2;
            #pragma unroll
            for (int o = 16; o; o >>= 1) {
                s  += __shfl_xor_sync(0xffffffffu, s, o);
                s2 += __shfl_xor_sync(0xffffffffu, s2, o);
            }
            float mu = s * (1.f / 96.f);
            float rs = rsqrtf(s2 * (1.f / 96.f) - mu * mu + 1e-5f);
            sA[n * 104 + lane]      = __float2bfloat16((v0 - mu) * rs * wv0 + bv0);
            sA[n * 104 + lane + 32] = __float2bfloat16((v1 - mu) * rs * wv1 + bv1);
            sA[n * 104 + lane + 64] = __float2bfloat16((v2 - mu) * rs * wv2 + bv2);
        }
    }

    const int win = w >> 2;
    const int wl  = w & 3;

    const uint32_t aA_u = smem_u + AB_SA + (uint32_t)(((w * 16 + arow) * 104 + acol) * 2);
    const uint32_t bWrel = (uint32_t)((brow * 104 + bcol) * 2);
    const uint32_t bK_u = smem_u + AB_SK + (uint32_t)(((win * 64 + brow) * 40 + bcol) * 2);
    const uint32_t bV_u = smem_u + AB_SVT + (uint32_t)((brow * 136 + win * 64 + bcol) * 2);
    const uint32_t bW1rel = (uint32_t)((brow * 104 + bcol) * 2);
    const uint32_t bW2rel = (uint32_t)((brow * 40 + bcol) * 2);

    // head-invariant softmax metadata: rows, and 16-bit region-equality masks
    const int tokr0 = wl * 16 + g, tokr1 = tokr0 + 8;
    const int iq0 = tokr0 >> 3, jq0 = tokr0 & 7;
    const int iq1 = tokr1 >> 3, jq1 = tokr1 & 7;
    uint32_t mask0 = 0, mask1 = 0;
    {
        int reg0 = sReg[win * 64 + tokr0], reg1 = sReg[win * 64 + tokr1];
        #pragma unroll
        for (int nt = 0; nt < 8; ++nt) {
            #pragma unroll
            for (int jj = 0; jj < 2; ++jj) {
                int m = nt * 8 + 2 * t + jj;
                int regm = sReg[win * 64 + m];
                int b = nt * 2 + jj;
                mask0 |= (uint32_t)(regm == reg0) << b;
                mask1 |= (uint32_t)(regm == reg1) << b;
            }
        }
    }

    float oacc[12][4];
    #pragma unroll
    for (int i = 0; i < 12; ++i)
        #pragma unroll
        for (int j = 0; j < 4; ++j) oacc[i][j] = 0.f;

    // =================== Phase A: attention ===================
    for (int h = 0; h < 3; ++h) {
        CP_WAIT0();
        __syncthreads();   // weights buf h&1 visible; prev head's K/Vt consumers done

        if (h < 2) {
            uint32_t dstb = smem_u + ((h & 1) ? AB_SW0 : AB_SW1);
            const char* srcb = (const char*)g_wqkv + (h + 1) * 19968;
            for (int i = tid; i < 1248; i += 256) cp16(dstb + i * 16, srcb + i * 16);
        } else {
            uint32_t dstb = smem_u + AB_SW1;
            const char* srcb = (const char*)g_wproj;
            for (int i = tid; i < 1248; i += 256) cp16(dstb + i * 16, srcb + i * 16);
        }
        CP_COMMIT();

        const uint32_t bW_u = smem_u + ((h & 1) ? AB_SW1 : AB_SW0) + bWrel;

        // ---- QKV GEMM: d(16 x 96) ----
        float d[12][4];
        #pragma unroll
        for (int i = 0; i < 12; ++i)
            #pragma unroll
            for (int j = 0; j < 4; ++j) d[i][j] = 0.f;
        #pragma unroll
        for (int kt = 0; kt < 6; ++kt) {
            uint32_t a0, a1, a2, a3;
            ldm_x4(a0, a1, a2, a3, aA_u + kt * 32);
            #pragma unroll
            for (int p = 0; p < 6; ++p) {
                uint32_t b0, b1r, b2, b3;
                ldm_x4(b0, b1r, b2, b3, bW_u + p * 3328 + kt * 32);
                mma_bf16(d[2 * p],     a0, a1, a2, a3, b0, b1r);
                mma_bf16(d[2 * p + 1], a0, a1, a2, a3, b2, b3);
            }
        }
        // epilogue: Q -> regs (scaled), K -> smem, V^T -> smem
        uint32_t qp[4][2];
        #pragma unroll
        for (int nt = 0; nt < 12; ++nt) {
            int c = nt * 8 + 2 * t;
            float bb0 = sBQ[h * 96 + c], bb1 = sBQ[h * 96 + c + 1];
            float v0 = d[nt][0] + bb0, v1 = d[nt][1] + bb1;
            float v2 = d[nt][2] + bb0, v3 = d[nt][3] + bb1;
            if (nt < 4) {
                qp[nt][0] = pack_bf16(v0 * scale, v1 * scale);
                qp[nt][1] = pack_bf16(v2 * scale, v3 * scale);
            } else if (nt < 8) {
                int dim = c - 32;
                *(uint32_t*)(sK + rowA * 40       + dim) = pack_bf16(v0, v1);
                *(uint32_t*)(sK + (rowA + 8) * 40 + dim) = pack_bf16(v2, v3);
            } else {
                int dim = c - 64;
                sVt[dim * 136 + rowA]           = __float2bfloat16(v0);
                sVt[(dim + 1) * 136 + rowA]     = __float2bfloat16(v1);
                sVt[dim * 136 + rowA + 8]       = __float2bfloat16(v2);
                sVt[(dim + 1) * 136 + rowA + 8] = __float2bfloat16(v3);
            }
        }
        WIN_BAR(1 + win);   // publish K / Vt within this window only

        // ---- scores: S(16 x 64) = Q @ K^T ----
        float d1[8][4];
        #pragma unroll
        for (int i = 0; i < 8; ++i)
            #pragma unroll
            for (int j = 0; j < 4; ++j) d1[i][j] = 0.f;
        #pragma unroll
        for (int kt = 0; kt < 2; ++kt) {
            uint32_t a0 = qp[2 * kt][0], a1 = qp[2 * kt][1];
            uint32_t a2 = qp[2 * kt + 1][0], a3 = qp[2 * kt + 1][1];
            #pragma unroll
            for (int p = 0; p < 4; ++p) {
                uint32_t b0, b1r, b2, b3;
                ldm_x4(b0, b1r, b2, b3, bK_u + p * 1280 + kt * 32);
                mma_bf16(d1[2 * p],     a0, a1, a2, a3, b0, b1r);
                mma_bf16(d1[2 * p + 1], a0, a1, a2, a3, b2, b3);
            }
        }
        // rel-pos bias + shift mask + softmax
        {
            #pragma unroll
            for (int nt = 0; nt < 8; ++nt) {
                #pragma unroll
                for (int jj = 0; jj < 2; ++jj) {
                    int m = nt * 8 + 2 * t + jj;
                    int im = m >> 3, jm = m & 7;
                    int b = nt * 2 + jj;
                    d1[nt][jj]     += sRPB[((iq0 - im + 7) * 15 + (jq0 - jm + 7)) * 3 + h]
                                      + (((mask0 >> b) & 1u) ? 0.f : -100.f);
                    d1[nt][2 + jj] += sRPB[((iq1 - im + 7) * 15 + (jq1 - jm + 7)) * 3 + h]
                                      + (((mask1 >> b) & 1u) ? 0.f : -100.f);
                }
            }
            float mx0 = -1e30f, mx1 = -1e30f;
            #pragma unroll
            for (int nt = 0; nt < 8; ++nt) {
                mx0 = fmaxf(mx0, fmaxf(d1[nt][0], d1[nt][1]));
                mx1 = fmaxf(mx1, fmaxf(d1[nt][2], d1[nt][3]));
            }
            #pragma unroll
            for (int o = 1; o <= 2; o <<= 1) {
                mx0 = fmaxf(mx0, __shfl_xor_sync(0xffffffffu, mx0, o));
                mx1 = fmaxf(mx1, __shfl_xor_sync(0xffffffffu, mx1, o));
            }
            float sum0 = 0.f, sum1 = 0.f;
            #pragma unroll
            for (int nt = 0; nt < 8; ++nt) {
                d1[nt][0] = __expf(d1[nt][0] - mx0); sum0 += d1[nt][0];
                d1[nt][1] = __expf(d1[nt][1] - mx0); sum0 += d1[nt][1];
                d1[nt][2] = __expf(d1[nt][2] - mx1); sum1 += d1[nt][2];
                d1[nt][3] = __expf(d1[nt][3] - mx1); sum1 += d1[nt][3];
            }
            #pragma unroll
            for (int o = 1; o <= 2; o <<= 1) {
                sum0 += __shfl_xor_sync(0xffffffffu, sum0, o);
                sum1 += __shfl_xor_sync(0xffffffffu, sum1, o);
            }
            float inv0 = 1.f / sum0, inv1 = 1.f / sum1;
            uint32_t pp[8][2];
            #pragma unroll
            for (int nt = 0; nt < 8; ++nt) {
                pp[nt][0] = pack_bf16(d1[nt][0] * inv0, d1[nt][1] * inv0);
                pp[nt][1] = pack_bf16(d1[nt][2] * inv1, d1[nt][3] * inv1);
            }
            // ---- PV ----
            #pragma unroll
            for (int kt = 0; kt < 4; ++kt) {
                uint32_t a0 = pp[2 * kt][0], a1 = pp[2 * kt][1];
                uint32_t a2 = pp[2 * kt + 1][0], a3 = pp[2 * kt + 1][1];
                #pragma unroll
                for (int p = 0; p < 2; ++p) {
                    uint32_t b0, b1r, b2, b3;
                    ldm_x4(b0, b1r, b2, b3, bV_u + p * 4352 + kt * 32);
                    mma_bf16(oacc[h * 4 + 2 * p],     a0, a1, a2, a3, b0, b1r);
                    mma_bf16(oacc[h * 4 + 2 * p + 1], a0, a1, a2, a3, b2, b3);
                }
            }
        }
    }

    // ---- proj: A-frags from oacc regs, weights in buf1 ----
    CP_WAIT0();
    __syncthreads();
    const int src0 = sSrc[rowA], src1 = sSrc[rowA + 8];
    uint32_t op[12][2];
    #pragma unroll
    for (int nt = 0; nt < 12; ++nt) {
        op[nt][0] = pack_bf16(oacc[nt][0], oacc[nt][1]);
        op[nt][1] = pack_bf16(oacc[nt][2], oacc[nt][3]);
    }
    float dproj[12][4];
    #pragma unroll
    for (int i = 0; i < 12; ++i)
        #pragma unroll
        for (int j = 0; j < 4; ++j) dproj[i][j] = 0.f;
    {
        const uint32_t bWp_u = smem_u + AB_SW1 + bWrel;
        #pragma unroll
        for (int kt = 0; kt < 6; ++kt) {
            uint32_t a0 = op[2 * kt][0], a1 = op[2 * kt][1];
            uint32_t a2 = op[2 * kt + 1][0], a3 = op[2 * kt + 1][1];
            #pragma unroll
            for (int p = 0; p < 6; ++p) {
                uint32_t b0, b1r, b2, b3;
                ldm_x4(b0, b1r, b2, b3, bWp_u + p * 3328 + kt * 32);
                mma_bf16(dproj[2 * p],     a0, a1, a2, a3, b0, b1r);
                mma_bf16(dproj[2 * p + 1], a0, a1, a2, a3, b2, b3);
            }
        }
    }
    __syncthreads();   // everyone done with phase-A smem before overlay

    // =================== Phase B: x1 + LN2 + MLP (4-buffer pipelined) ===================
    // prefetch chunks 0 and 1 (two groups)
    for (int i = tid; i < 416; i += 256) cp16(smem_u + PB_W1 + i * 16, (const char*)g_w1 + i * 16);
    for (int i = tid; i < 480; i += 256) cp16(smem_u + PB_W2 + i * 16, (const char*)g_w2 + i * 16);
    CP_COMMIT();
    for (int i = tid; i < 416; i += 256) cp16(smem_u + PB_W1 + 6656 + i * 16, (const char*)g_w1 + 6656 + i * 16);
    for (int i = tid; i < 480; i += 256) cp16(smem_u + PB_W2 + 7680 + i * 16, (const char*)g_w2 + 7680 + i * 16);
    CP_COMMIT();

    // x1 = proj + pb + x (regs + sX1 store); LN2 in regs -> xp A-frags
    uint32_t xp[12][2];
    {
        const float* px0 = x + (size_t)src0 * 96;
        const float* px1 = x + (size_t)src1 * 96;
        float x1v[12][4];
        float s0 = 0.f, q0 = 0.f, s1 = 0.f, q1 = 0.f;
        #pragma unroll
        for (int nt = 0; nt < 12; ++nt) {
            int c = nt * 8 + 2 * t;
            float bb0 = sBP[c], bb1 = sBP[c + 1];
            float2 xa = *(const float2*)(px0 + c);
            float2 xb = *(const float2*)(px1 + c);
            float v0 = dproj[nt][0] + bb0 + xa.x;
            float v1 = dproj[nt][1] + bb1 + xa.y;
            float v2 = dproj[nt][2] + bb0 + xb.x;
            float v3 = dproj[nt][3] + bb1 + xb.y;
            x1v[nt][0] = v0; x1v[nt][1] = v1; x1v[nt][2] = v2; x1v[nt][3] = v3;
            float2 r1; r1.x = v0; r1.y = v1;
            float2 r2; r2.x = v2; r2.y = v3;
            *(float2*)(sX1 + rowA * 98 + c)       = r1;
            *(float2*)(sX1 + (rowA + 8) * 98 + c) = r2;
            s0 += v0 + v1;  q0 += v0 * v0 + v1 * v1;
            s1 += v2 + v3;  q1 += v2 * v2 + v3 * v3;
        }
        #pragma unroll
        for (int o = 1; o <= 2; o <<= 1) {
            s0 += __shfl_xor_sync(0xffffffffu, s0, o);
            q0 += __shfl_xor_sync(0xffffffffu, q0, o);
            s1 += __shfl_xor_sync(0xffffffffu, s1, o);
            q1 += __shfl_xor_sync(0xffffffffu, q1, o);
        }
        float mu0 = s0 * (1.f / 96.f), mu1 = s1 * (1.f / 96.f);
        float rs0 = rsqrtf(q0 * (1.f / 96.f) - mu0 * mu0 + 1e-5f);
        float rs1 = rsqrtf(q1 * (1.f / 96.f) - mu1 * mu1 + 1e-5f);
        #pragma unroll
        for (int nt = 0; nt < 12; ++nt) {
            int c = nt * 8 + 2 * t;
            float w0v = sN2W[c], w1v = sN2W[c + 1];
            float b0v = sN2B[c], b1v = sN2B[c + 1];
            xp[nt][0] = pack_bf16((x1v[nt][0] - mu0) * rs0 * w0v + b0v,
                                  (x1v[nt][1] - mu0) * rs0 * w1v + b1v);
            xp[nt][1] = pack_bf16((x1v[nt][2] - mu1) * rs1 * w0v + b0v,
                                  (x1v[nt][3] - mu1) * rs1 * w1v + b1v);
        }
    }
    // stage fc biases
    for (int i = tid; i < 384; i += 256) sB1[i] = b1[i];
    if (tid < 96) sB2[tid] = b2[tid];

    // wait chunk 0 (keep chunk 1 in flight), publish, then pre-compute GEMM1(chunk 0)
    CP_WAIT1();
    __syncthreads();

    float d2[12][4];
    #pragma unroll
    for (int i = 0; i < 12; ++i)
        #pragma unroll
        for (int j = 0; j < 4; ++j) d2[i][j] = 0.f;

    float d1p[4][4];
    #pragma unroll
    for (int i = 0; i < 4; ++i)
        #pragma unroll
        for (int j = 0; j < 4; ++j) d1p[i][j] = 0.f;
    {
        const uint32_t bW1_u = smem_u + PB_W1 + bW1rel;   // buffer 0
        #pragma unroll
        for (int kt = 0; kt < 6; ++kt) {
            uint32_t a0 = xp[2 * kt][0], a1 = xp[2 * kt][1];
            uint32_t a2 = xp[2 * kt + 1][0], a3 = xp[2 * kt + 1][1];
            #pragma unroll
            for (int p = 0; p < 2; ++p) {
                uint32_t b0, b1r, b2, b3;
                ldm_x4(b0, b1r, b2, b3, bW1_u + p * 3328 + kt * 32);
                mma_bf16(d1p[2 * p],     a0, a1, a2, a3, b0, b1r);
                mma_bf16(d1p[2 * p + 1], a0, a1, a2, a3, b2, b3);
            }
        }
    }

    for (int nc = 0; nc < 12; ++nc) {
        // prefetch chunk nc+2 into buffer (nc+2)&3 (target retired 2 iterations ago)
        if (nc + 2 <= 11) {
            uint32_t b = (uint32_t)((nc + 2) & 3);
            const char* s1c = (const char*)g_w1 + (nc + 2) * 6656;
            const char* s2c = (const char*)g_w2 + (nc + 2) * 7680;
            for (int i = tid; i < 416; i += 256) cp16(smem_u + PB_W1 + b * 6656 + i * 16, s1c + i * 16);
            for (int i = tid; i < 480; i += 256) cp16(smem_u + PB_W2 + b * 7680 + i * 16, s2c + i * 16);
            CP_COMMIT();
        }
        // need chunk nc+1's buffers ready for the lookahead GEMM1
        if (nc >= 10) { CP_WAIT0(); } else { CP_WAIT1(); }
        __syncthreads();

        // GELU of chunk nc (from d1p computed last iteration)
        uint32_t hp[4][2];
        #pragma unroll
        for (int nt = 0; nt < 4; ++nt) {
            int c = nt * 8 + 2 * t;
            float bb0 = sB1[nc * 32 + c], bb1 = sB1[nc * 32 + c + 1];
            hp[nt][0] = pack_bf16(gelu_fast(d1p[nt][0] + bb0), gelu_fast(d1p[nt][1] + bb1));
            hp[nt][1] = pack_bf16(gelu_fast(d1p[nt][2] + bb0), gelu_fast(d1p[nt][3] + bb1));
        }

        // lookahead GEMM1 for chunk nc+1 (independent stream)
        if (nc < 11) {
            #pragma unroll
            for (int i = 0; i < 4; ++i)
                #pragma unroll
                for (int j = 0; j < 4; ++j) d1p[i][j] = 0.f;
            const uint32_t bW1_u = smem_u + PB_W1 + (uint32_t)(((nc + 1) & 3) * 6656) + bW1rel;
            #pragma unroll
            for (int kt = 0; kt < 6; ++kt) {
                uint32_t a0 = xp[2 * kt][0], a1 = xp[2 * kt][1];
                uint32_t a2 = xp[2 * kt + 1][0], a3 = xp[2 * kt + 1][1];
                #pragma unroll
                for (int p = 0; p < 2; ++p) {
                    uint32_t b0, b1r, b2, b3;
                    ldm_x4(b0, b1r, b2, b3, bW1_u + p * 3328 + kt * 32);
                    mma_bf16(d1p[2 * p],     a0, a1, a2, a3, b0, b1r);
                    mma_bf16(d1p[2 * p + 1], a0, a1, a2, a3, b2, b3);
                }
            }
        }

        // GEMM2 of chunk nc
        {
            const uint32_t bW2_u = smem_u + PB_W2 + (uint32_t)((nc & 3) * 7680) + bW2rel;
            #pragma unroll
            for (int kt = 0; kt < 2; ++kt) {
                uint32_t a0 = hp[2 * kt][0], a1 = hp[2 * kt][1];
                uint32_t a2 = hp[2 * kt + 1][0], a3 = hp[2 * kt + 1][1];
                #pragma unroll
                for (int p = 0; p < 6; ++p) {
                    uint32_t b0, b1r, b2, b3;
                    ldm_x4(b0, b1r, b2, b3, bW2_u + p * 1280 + kt * 32);
                    mma_bf16(d2[2 * p],     a0, a1, a2, a3, b0, b1r);
                    mma_bf16(d2[2 * p + 1], a0, a1, a2, a3, b2, b3);
                }
            }
        }
    }

    // ---- final: out = d2 + b2 + x1 (sX1 own rows), scatter ----
    {
        float* po0 = out + (size_t)src0 * 96;
        float* po1 = out + (size_t)src1 * 96;
        #pragma unroll
        for (int nt = 0; nt < 12; ++nt) {
            int c = nt * 8 + 2 * t;
            float bb0 = sB2[c], bb1 = sB2[c + 1];
            float2 xa = *(const float2*)(sX1 + rowA * 98 + c);
            float2 xb = *(const float2*)(sX1 + (rowA + 8) * 98 + c);
            float2 r1, r2;
            r1.x = d2[nt][0] + bb0 + xa.x;  r1.y = d2[nt][1] + bb1 + xa.y;
            r2.x = d2[nt][2] + bb0 + xb.x;  r2.y = d2[nt][3] + bb1 + xb.y;
            *(float2*)(po0 + c) = r1;
            *(float2*)(po1 + c) = r2;
        }
    }
}

extern "C" void kernel_launch(void* const* d_in, const int* in_sizes, int n_in,
                              void* d_out, int out_size)
{
    const float* x    = (const float*)d_in[0];
    const float* n1w  = (const float*)d_in[1];
    const float* n1b  = (const float*)d_in[2];
    const float* qkvw = (const float*)d_in[3];
    const float* qkvb = (const float*)d_in[4];
    const float* rpb  = (const float*)d_in[5];
    const float* pw   = (const float*)d_in[6];
    const float* pb   = (const float*)d_in[7];
    const float* n2w  = (const float*)d_in[8];
    const float* n2b  = (const float*)d_in[9];
    const float* w1   = (const float*)d_in[10];
    const float* b1   = (const float*)d_in[11];
    const float* w2   = (const float*)d_in[12];
    const float* b2   = (const float*)d_in[13];
    float* out = (float*)d_out;

    cudaFuncSetAttribute(block_kernel, cudaFuncAttributeMaxDynamicSharedMemorySize, SM_BYTES);

    prep_kernel<<<64, 256>>>(qkvw, pw, w1, w2);
    block_kernel<<<2048, 256, SM_BYTES>>>(x, n1w, n1b, qkvb, rpb, pb, n2w, n2b, b1, b2, out);
}

// round 16
// speedup vs baseline: 1.0530x; 1.0530x over previous
#include <cuda_runtime.h>
#include <cuda_bf16.h>
#include <math.h>
#include <stdint.h>

// pre-converted bf16 weights in smem-ready layouts (written by prep_kernel each launch)
static __device__ __align__(16) __nv_bfloat16 g_wqkv[3 * 96 * 104];  // [h][n][k], stride 104
static __device__ __align__(16) __nv_bfloat16 g_wproj[96 * 104];     // [n][k]
static __device__ __align__(16) __nv_bfloat16 g_w1[12 * 32 * 104];   // [nc][n][k]
static __device__ __align__(16) __nv_bfloat16 g_w2[12 * 96 * 40];    // [nc][n][k]

__global__ void prep_kernel(
    const float* __restrict__ qkvw, const float* __restrict__ pw,
    const float* __restrict__ w1,   const float* __restrict__ w2)
{
    const int stride = gridDim.x * blockDim.x;
    const int tid0 = blockIdx.x * blockDim.x + threadIdx.x;
    for (int i = tid0; i < 3 * 96 * 96; i += stride) {
        int h = i / 9216, r = i - h * 9216, n = r / 96, k = r - n * 96;
        int sec = n >> 5, d = n & 31;
        g_wqkv[h * 9984 + n * 104 + k] = __float2bfloat16(qkvw[k * 288 + sec * 96 + h * 32 + d]);
    }
    for (int i = tid0; i < 96 * 96; i += stride) {
        int n = i / 96, k = i - n * 96;
        g_wproj[n * 104 + k] = __float2bfloat16(pw[k * 96 + n]);
    }
    for (int i = tid0; i < 96 * 384; i += stride) {
        int k = i / 384, c = i - k * 384;
        int nc = c >> 5, n = c & 31;
        g_w1[nc * 3328 + n * 104 + k] = __float2bfloat16(w1[i]);
    }
    for (int i = tid0; i < 384 * 96; i += stride) {
        int kr = i / 96, n = i - kr * 96;
        int nc = kr >> 5, kk = kr & 31;
        g_w2[nc * 3840 + n * 40 + kk] = __float2bfloat16(w2[i]);
    }
}

// ===================== mma / ldmatrix / cp.async helpers =====================
__device__ __forceinline__ void mma_bf16(float d[4],
    uint32_t a0, uint32_t a1, uint32_t a2, uint32_t a3, uint32_t b0, uint32_t b1)
{
    asm volatile(
        "mma.sync.aligned.m16n8k16.row.col.f32.bf16.bf16.f32 "
        "{%0,%1,%2,%3},{%4,%5,%6,%7},{%8,%9},{%0,%1,%2,%3};"
        : "+f"(d[0]), "+f"(d[1]), "+f"(d[2]), "+f"(d[3])
        : "r"(a0), "r"(a1), "r"(a2), "r"(a3), "r"(b0), "r"(b1));
}
__device__ __forceinline__ void ldm_x4(uint32_t& r0, uint32_t& r1, uint32_t& r2, uint32_t& r3,
                                       uint32_t addr)
{
    asm volatile("ldmatrix.sync.aligned.m8n8.x4.shared.b16 {%0,%1,%2,%3}, [%4];"
                 : "=r"(r0), "=r"(r1), "=r"(r2), "=r"(r3) : "r"(addr));
}
__device__ __forceinline__ uint32_t pack_bf16(float lo, float hi) {
    uint32_t r;
    asm("cvt.rn.bf16x2.f32 %0, %1, %2;" : "=r"(r) : "f"(hi), "f"(lo)); // d.hi=%1, d.lo=%2
    return r;
}
__device__ __forceinline__ float gelu_fast(float v) {
    float u = v * (0.79788456f + 0.035677408f * v * v);
    float th; asm("tanh.approx.f32 %0, %1;" : "=f"(th) : "f"(u));
    return 0.5f * v * (1.f + th);
}
__device__ __forceinline__ void cp16(uint32_t dst, const void* src) {
    asm volatile("cp.async.cg.shared.global [%0], [%1], 16;" :: "r"(dst), "l"(src) : "memory");
}
#define CP_COMMIT() asm volatile("cp.async.commit_group;" ::: "memory")
#define CP_WAIT0()  asm volatile("cp.async.wait_group 0;" ::: "memory")
#define WIN_BAR(id) asm volatile("bar.sync %0, 128;" :: "r"(id) : "memory")

// ---------------- fused kernel smem layout (bytes) ----------------
// Phase A:
constexpr uint32_t AB_SA  = 0;        // 128 x 104 bf16 LN1 tokens      (26624)
constexpr uint32_t AB_SW0 = 26624;    // weight buf 0: 96 x 104 bf16    (19968)
constexpr uint32_t AB_SW1 = 46592;    // weight buf 1                   (19968) -> 66560
constexpr uint32_t AB_SK  = 66560;    // 128 x 40 bf16                  (10240) -> 76800
constexpr uint32_t AB_SVT = 76800;    // 32 x 136 bf16                  (8704)  -> 85504
constexpr uint32_t AB_RPB = 85504;    // 675 f32                        -> 88208 (pad)
constexpr uint32_t AB_REG = 88208;    // 128 int                        -> 88720
constexpr uint32_t AB_BQ  = 88720;    // 288 f32 qkv bias (per-head)    -> 89872
// Phase B (overlays phase A up to 109440):
constexpr uint32_t PB_X1  = 0;        // x1 f32 128 x stride 98         (50176)
constexpr uint32_t PB_W1  = 50176;    // 4 x (32 x 104 bf16 = 6656)     -> 76800
constexpr uint32_t PB_W2  = 76800;    // 4 x (96 x 40 bf16 = 7680)      -> 107520
constexpr uint32_t PB_B1  = 107520;   // 384 f32 fc1 bias               -> 109056
constexpr uint32_t PB_B2  = 109056;   // 96 f32 fc2 bias                -> 109440
// Persistent (never overlaid):
constexpr uint32_t PS_SRC = 109440;   // 128 int                        -> 109952
constexpr uint32_t PS_BP  = 109952;   // 96 f32 proj bias               -> 110336
constexpr uint32_t PS_N2W = 110336;   // 96 f32                         -> 110720
constexpr uint32_t PS_N2B = 110720;   // 96 f32                         -> 111104
constexpr uint32_t SM_BYTES = 111104;

__global__ __launch_bounds__(256, 2) void block_kernel(
    const float* __restrict__ x,
    const float* __restrict__ n1w, const float* __restrict__ n1b,
    const float* __restrict__ qkvb,
    const float* __restrict__ rpb,
    const float* __restrict__ pb,
    const float* __restrict__ n2w, const float* __restrict__ n2b,
    const float* __restrict__ b1,  const float* __restrict__ b2,
    float* __restrict__ out)
{
    extern __shared__ char smc[];
    __nv_bfloat16* sA  = (__nv_bfloat16*)(smc + AB_SA);
    __nv_bfloat16* sK  = (__nv_bfloat16*)(smc + AB_SK);
    __nv_bfloat16* sVt = (__nv_bfloat16*)(smc + AB_SVT);
    float* sRPB = (float*)(smc + AB_RPB);
    int*   sReg = (int*)(smc + AB_REG);
    int*   sSrc = (int*)(smc + PS_SRC);
    float* sBQ  = (float*)(smc + AB_BQ);
    float* sBP  = (float*)(smc + PS_BP);
    float* sN2W = (float*)(smc + PS_N2W);
    float* sN2B = (float*)(smc + PS_N2B);
    float* sX1  = (float*)(smc + PB_X1);
    float* sB1  = (float*)(smc + PB_B1);
    float* sB2  = (float*)(smc + PB_B2);

    const uint32_t smem_u = (uint32_t)__cvta_generic_to_shared(smc);

    const int tid  = threadIdx.x;
    const int w    = tid >> 5;
    const int lane = tid & 31;
    const int g    = lane >> 2;
    const int t    = lane & 3;
    const int rowA = w * 16 + g;

    // ldmatrix per-lane tile coords
    const int quad = lane >> 3, qr = lane & 7;
    const int arow = (quad & 1) * 8 + qr;
    const int acol = (quad >> 1) * 8;
    const int brow = (quad >> 1) * 8 + qr;
    const int bcol = (quad & 1) * 8;

    const int bw  = blockIdx.x;
    const int bb  = bw >> 7;
    const int wh  = (bw >> 3) & 15;
    const int wwp = bw & 7;
    const float scale = 0.17677669529663687f;

    // kick off head-0 weight staging immediately
    for (int i = tid; i < 1248; i += 256)
        cp16(smem_u + AB_SW0 + i * 16, (const char*)g_wqkv + i * 16);
    CP_COMMIT();

    // metadata + bias staging
    if (tid < 128) {
        int win0 = tid >> 6, tok = tid & 63;
        int i = tok >> 3, j = tok & 7;
        int hr = wh * 8 + i, wr = (wwp * 2 + win0) * 8 + j;
        int hs = (hr + 4) & 127, ws = (wr + 4) & 127;
        sSrc[tid] = bb * 16384 + hs * 128 + ws;
        int rh = hr < 120 ? 0 : (hr < 124 ? 1 : 2);
        int rw = wr < 120 ? 0 : (wr < 124 ? 1 : 2);
        sReg[tid] = rh * 3 + rw;
    }
    for (int q = tid; q < 675; q += 256) sRPB[q] = rpb[q];
    for (int i = tid; i < 288; i += 256) {
        int h = i / 96, n = i - h * 96;
        sBQ[i] = qkvb[(n >> 5) * 96 + h * 32 + (n & 31)];
    }
    if (tid < 96) { sBP[tid] = pb[tid]; sN2W[tid] = n2w[tid]; sN2B[tid] = n2b[tid]; }
    __syncthreads();

    // gather + LN1 -> sA bf16 (own-warp rows)
    {
        float wv0 = n1w[lane], wv1 = n1w[lane + 32], wv2 = n1w[lane + 64];
        float bv0 = n1b[lane], bv1 = n1b[lane + 32], bv2 = n1b[lane + 64];
        for (int rr = 0; rr < 16; ++rr) {
            int n = w * 16 + rr;
            const float* px = x + (size_t)sSrc[n] * 96;
            float v0 = px[lane], v1 = px[lane + 32], v2 = px[lane + 64];
            float s = v0 + v1 + v2, s2 = v0 * v0 + v1 * v1 + v2 * v2;
            #pragma unroll
            for (int o = 16; o; o >>= 1) {
                s  += __shfl_xor_sync(0xffffffffu, s, o);
                s2 += __shfl_xor_sync(0xffffffffu, s2, o);
            }
            float mu = s * (1.f / 96.f);
            float rs = rsqrtf(s2 * (1.f / 96.f) - mu * mu + 1e-5f);
            sA[n * 104 + lane]      = __float2bfloat16((v0 - mu) * rs * wv0 + bv0);
            sA[n * 104 + lane + 32] = __float2bfloat16((v1 - mu) * rs * wv1 + bv1);
            sA[n * 104 + lane + 64] = __float2bfloat16((v2 - mu) * rs * wv2 + bv2);
        }
    }

    const int win = w >> 2;
    const int wl  = w & 3;

    const uint32_t aA_u = smem_u + AB_SA + (uint32_t)(((w * 16 + arow) * 104 + acol) * 2);
    const uint32_t bWrel = (uint32_t)((brow * 104 + bcol) * 2);
    const uint32_t bK_u = smem_u + AB_SK + (uint32_t)(((win * 64 + brow) * 40 + bcol) * 2);
    const uint32_t bV_u = smem_u + AB_SVT + (uint32_t)((brow * 136 + win * 64 + bcol) * 2);
    const uint32_t bW1rel = (uint32_t)((brow * 104 + bcol) * 2);
    const uint32_t bW2rel = (uint32_t)((brow * 40 + bcol) * 2);

    // head-invariant softmax metadata: rows, and 16-bit region-equality masks
    const int tokr0 = wl * 16 + g, tokr1 = tokr0 + 8;
    const int iq0 = tokr0 >> 3, jq0 = tokr0 & 7;
    const int iq1 = tokr1 >> 3, jq1 = tokr1 & 7;
    uint32_t mask0 = 0, mask1 = 0;
    {
        int reg0 = sReg[win * 64 + tokr0], reg1 = sReg[win * 64 + tokr1];
        #pragma unroll
        for (int nt = 0; nt < 8; ++nt) {
            #pragma unroll
            for (int jj = 0; jj < 2; ++jj) {
                int m = nt * 8 + 2 * t + jj;
                int regm = sReg[win * 64 + m];
                int b = nt * 2 + jj;
                mask0 |= (uint32_t)(regm == reg0) << b;
                mask1 |= (uint32_t)(regm == reg1) << b;
            }
        }
    }

    float oacc[12][4];
    #pragma unroll
    for (int i = 0; i < 12; ++i)
        #pragma unroll
        for (int j = 0; j < 4; ++j) oacc[i][j] = 0.f;

    // =================== Phase A: attention ===================
    for (int h = 0; h < 3; ++h) {
        CP_WAIT0();
        __syncthreads();   // weights buf h&1 visible; prev head's K/Vt consumers done

        if (h < 2) {
            uint32_t dstb = smem_u + ((h & 1) ? AB_SW0 : AB_SW1);
            const char* srcb = (const char*)g_wqkv + (h + 1) * 19968;
            for (int i = tid; i < 1248; i += 256) cp16(dstb + i * 16, srcb + i * 16);
        } else {
            uint32_t dstb = smem_u + AB_SW1;
            const char* srcb = (const char*)g_wproj;
            for (int i = tid; i < 1248; i += 256) cp16(dstb + i * 16, srcb + i * 16);
        }
        CP_COMMIT();

        const uint32_t bW_u = smem_u + ((h & 1) ? AB_SW1 : AB_SW0) + bWrel;

        // ---- QKV GEMM: d(16 x 96) ----
        float d[12][4];
        #pragma unroll
        for (int i = 0; i < 12; ++i)
            #pragma unroll
            for (int j = 0; j < 4; ++j) d[i][j] = 0.f;
        #pragma unroll
        for (int kt = 0; kt < 6; ++kt) {
            uint32_t a0, a1, a2, a3;
            ldm_x4(a0, a1, a2, a3, aA_u + kt * 32);
            #pragma unroll
            for (int p = 0; p < 6; ++p) {
                uint32_t b0, b1r, b2, b3;
                ldm_x4(b0, b1r, b2, b3, bW_u + p * 3328 + kt * 32);
                mma_bf16(d[2 * p],     a0, a1, a2, a3, b0, b1r);
                mma_bf16(d[2 * p + 1], a0, a1, a2, a3, b2, b3);
            }
        }
        // epilogue: Q -> regs (scaled), K -> smem, V^T -> smem
        uint32_t qp[4][2];
        #pragma unroll
        for (int nt = 0; nt < 12; ++nt) {
            int c = nt * 8 + 2 * t;
            float bb0 = sBQ[h * 96 + c], bb1 = sBQ[h * 96 + c + 1];
            float v0 = d[nt][0] + bb0, v1 = d[nt][1] + bb1;
            float v2 = d[nt][2] + bb0, v3 = d[nt][3] + bb1;
            if (nt < 4) {
                qp[nt][0] = pack_bf16(v0 * scale, v1 * scale);
                qp[nt][1] = pack_bf16(v2 * scale, v3 * scale);
            } else if (nt < 8) {
                int dim = c - 32;
                *(uint32_t*)(sK + rowA * 40       + dim) = pack_bf16(v0, v1);
                *(uint32_t*)(sK + (rowA + 8) * 40 + dim) = pack_bf16(v2, v3);
            } else {
                int dim = c - 64;
                sVt[dim * 136 + rowA]           = __float2bfloat16(v0);
                sVt[(dim + 1) * 136 + rowA]     = __float2bfloat16(v1);
                sVt[dim * 136 + rowA + 8]       = __float2bfloat16(v2);
                sVt[(dim + 1) * 136 + rowA + 8] = __float2bfloat16(v3);
            }
        }
        WIN_BAR(1 + win);   // publish K / Vt within this window only

        // ---- scores: S(16 x 64) = Q @ K^T ----
        float d1[8][4];
        #pragma unroll
        for (int i = 0; i < 8; ++i)
            #pragma unroll
            for (int j = 0; j < 4; ++j) d1[i][j] = 0.f;
        #pragma unroll
        for (int kt = 0; kt < 2; ++kt) {
            uint32_t a0 = qp[2 * kt][0], a1 = qp[2 * kt][1];
            uint32_t a2 = qp[2 * kt + 1][0], a3 = qp[2 * kt + 1][1];
            #pragma unroll
            for (int p = 0; p < 4; ++p) {
                uint32_t b0, b1r, b2, b3;
                ldm_x4(b0, b1r, b2, b3, bK_u + p * 1280 + kt * 32);
                mma_bf16(d1[2 * p],     a0, a1, a2, a3, b0, b1r);
                mma_bf16(d1[2 * p + 1], a0, a1, a2, a3, b2, b3);
            }
        }
        // rel-pos bias + shift mask + softmax
        {
            #pragma unroll
            for (int nt = 0; nt < 8; ++nt) {
                #pragma unroll
                for (int jj = 0; jj < 2; ++jj) {
                    int m = nt * 8 + 2 * t + jj;
                    int im = m >> 3, jm = m & 7;
                    int b = nt * 2 + jj;
                    d1[nt][jj]     += sRPB[((iq0 - im + 7) * 15 + (jq0 - jm + 7)) * 3 + h]
                                      + (((mask0 >> b) & 1u) ? 0.f : -100.f);
                    d1[nt][2 + jj] += sRPB[((iq1 - im + 7) * 15 + (jq1 - jm + 7)) * 3 + h]
                                      + (((mask1 >> b) & 1u) ? 0.f : -100.f);
                }
            }
            float mx0 = -1e30f, mx1 = -1e30f;
            #pragma unroll
            for (int nt = 0; nt < 8; ++nt) {
                mx0 = fmaxf(mx0, fmaxf(d1[nt][0], d1[nt][1]));
                mx1 = fmaxf(mx1, fmaxf(d1[nt][2], d1[nt][3]));
            }
            #pragma unroll
            for (int o = 1; o <= 2; o <<= 1) {
                mx0 = fmaxf(mx0, __shfl_xor_sync(0xffffffffu, mx0, o));
                mx1 = fmaxf(mx1, __shfl_xor_sync(0xffffffffu, mx1, o));
            }
            float sum0 = 0.f, sum1 = 0.f;
            #pragma unroll
            for (int nt = 0; nt < 8; ++nt) {
                d1[nt][0] = __expf(d1[nt][0] - mx0); sum0 += d1[nt][0];
                d1[nt][1] = __expf(d1[nt][1] - mx0); sum0 += d1[nt][1];
                d1[nt][2] = __expf(d1[nt][2] - mx1); sum1 += d1[nt][2];
                d1[nt][3] = __expf(d1[nt][3] - mx1); sum1 += d1[nt][3];
            }
            #pragma unroll
            for (int o = 1; o <= 2; o <<= 1) {
                sum0 += __shfl_xor_sync(0xffffffffu, sum0, o);
                sum1 += __shfl_xor_sync(0xffffffffu, sum1, o);
            }
            float inv0 = 1.f / sum0, inv1 = 1.f / sum1;
            uint32_t pp[8][2];
            #pragma unroll
            for (int nt = 0; nt < 8; ++nt) {
                pp[nt][0] = pack_bf16(d1[nt][0] * inv0, d1[nt][1] * inv0);
                pp[nt][1] = pack_bf16(d1[nt][2] * inv1, d1[nt][3] * inv1);
            }
            // ---- PV ----
            #pragma unroll
            for (int kt = 0; kt < 4; ++kt) {
                uint32_t a0 = pp[2 * kt][0], a1 = pp[2 * kt][1];
                uint32_t a2 = pp[2 * kt + 1][0], a3 = pp[2 * kt + 1][1];
                #pragma unroll
                for (int p = 0; p < 2; ++p) {
                    uint32_t b0, b1r, b2, b3;
                    ldm_x4(b0, b1r, b2, b3, bV_u + p * 4352 + kt * 32);
                    mma_bf16(oacc[h * 4 + 2 * p],     a0, a1, a2, a3, b0, b1r);
                    mma_bf16(oacc[h * 4 + 2 * p + 1], a0, a1, a2, a3, b2, b3);
                }
            }
        }
    }

    // ---- proj: A-frags from oacc regs, weights in buf1 ----
    CP_WAIT0();
    __syncthreads();
    const int src0 = sSrc[rowA], src1 = sSrc[rowA + 8];
    uint32_t op[12][2];
    #pragma unroll
    for (int nt = 0; nt < 12; ++nt) {
        op[nt][0] = pack_bf16(oacc[nt][0], oacc[nt][1]);
        op[nt][1] = pack_bf16(oacc[nt][2], oacc[nt][3]);
    }
    float dproj[12][4];
    #pragma unroll
    for (int i = 0; i < 12; ++i)
        #pragma unroll
        for (int j = 0; j < 4; ++j) dproj[i][j] = 0.f;
    {
        const uint32_t bWp_u = smem_u + AB_SW1 + bWrel;
        #pragma unroll
        for (int kt = 0; kt < 6; ++kt) {
            uint32_t a0 = op[2 * kt][0], a1 = op[2 * kt][1];
            uint32_t a2 = op[2 * kt + 1][0], a3 = op[2 * kt + 1][1];
            #pragma unroll
            for (int p = 0; p < 6; ++p) {
                uint32_t b0, b1r, b2, b3;
                ldm_x4(b0, b1r, b2, b3, bWp_u + p * 3328 + kt * 32);
                mma_bf16(dproj[2 * p],     a0, a1, a2, a3, b0, b1r);
                mma_bf16(dproj[2 * p + 1], a0, a1, a2, a3, b2, b3);
            }
        }
    }
    __syncthreads();   // everyone done with phase-A smem before overlay

    // =================== Phase B: x1 + LN2 + MLP (4 buffers, 2 chunks per barrier) ===================
    // prefetch chunks 0 and 1 as ONE group
    for (int i = tid; i < 416; i += 256) cp16(smem_u + PB_W1 + i * 16, (const char*)g_w1 + i * 16);
    for (int i = tid; i < 480; i += 256) cp16(smem_u + PB_W2 + i * 16, (const char*)g_w2 + i * 16);
    for (int i = tid; i < 416; i += 256) cp16(smem_u + PB_W1 + 6656 + i * 16, (const char*)g_w1 + 6656 + i * 16);
    for (int i = tid; i < 480; i += 256) cp16(smem_u + PB_W2 + 7680 + i * 16, (const char*)g_w2 + 7680 + i * 16);
    CP_COMMIT();

    // x1 = proj + pb + x (regs + sX1 store); LN2 in regs -> xp A-frags
    uint32_t xp[12][2];
    {
        const float* px0 = x + (size_t)src0 * 96;
        const float* px1 = x + (size_t)src1 * 96;
        float x1v[12][4];
        float s0 = 0.f, q0 = 0.f, s1 = 0.f, q1 = 0.f;
        #pragma unroll
        for (int nt = 0; nt < 12; ++nt) {
            int c = nt * 8 + 2 * t;
            float bb0 = sBP[c], bb1 = sBP[c + 1];
            float2 xa = *(const float2*)(px0 + c);
            float2 xb = *(const float2*)(px1 + c);
            float v0 = dproj[nt][0] + bb0 + xa.x;
            float v1 = dproj[nt][1] + bb1 + xa.y;
            float v2 = dproj[nt][2] + bb0 + xb.x;
            float v3 = dproj[nt][3] + bb1 + xb.y;
            x1v[nt][0] = v0; x1v[nt][1] = v1; x1v[nt][2] = v2; x1v[nt][3] = v3;
            float2 r1; r1.x = v0; r1.y = v1;
            float2 r2; r2.x = v2; r2.y = v3;
            *(float2*)(sX1 + rowA * 98 + c)       = r1;
            *(float2*)(sX1 + (rowA + 8) * 98 + c) = r2;
            s0 += v0 + v1;  q0 += v0 * v0 + v1 * v1;
            s1 += v2 + v3;  q1 += v2 * v2 + v3 * v3;
        }
        #pragma unroll
        for (int o = 1; o <= 2; o <<= 1) {
            s0 += __shfl_xor_sync(0xffffffffu, s0, o);
            q0 += __shfl_xor_sync(0xffffffffu, q0, o);
            s1 += __shfl_xor_sync(0xffffffffu, s1, o);
            q1 += __shfl_xor_sync(0xffffffffu, q1, o);
        }
        float mu0 = s0 * (1.f / 96.f), mu1 = s1 * (1.f / 96.f);
        float rs0 = rsqrtf(q0 * (1.f / 96.f) - mu0 * mu0 + 1e-5f);
        float rs1 = rsqrtf(q1 * (1.f / 96.f) - mu1 * mu1 + 1e-5f);
        #pragma unroll
        for (int nt = 0; nt < 12; ++nt) {
            int c = nt * 8 + 2 * t;
            float w0v = sN2W[c], w1v = sN2W[c + 1];
            float b0v = sN2B[c], b1v = sN2B[c + 1];
            xp[nt][0] = pack_bf16((x1v[nt][0] - mu0) * rs0 * w0v + b0v,
                                  (x1v[nt][1] - mu0) * rs0 * w1v + b1v);
            xp[nt][1] = pack_bf16((x1v[nt][2] - mu1) * rs1 * w0v + b0v,
                                  (x1v[nt][3] - mu1) * rs1 * w1v + b1v);
        }
    }
    // stage fc biases
    for (int i = tid; i < 384; i += 256) sB1[i] = b1[i];
    if (tid < 96) sB2[tid] = b2[tid];

    float d2[12][4];
    #pragma unroll
    for (int i = 0; i < 12; ++i)
        #pragma unroll
        for (int j = 0; j < 4; ++j) d2[i][j] = 0.f;

    for (int ncp = 0; ncp < 12; ncp += 2) {
        CP_WAIT0();
        __syncthreads();   // chunks ncp, ncp+1 visible; buffers (ncp+2..3)&3 retired last iteration
        if (ncp + 2 < 12) {
            // prefetch chunks ncp+2, ncp+3 as one group
            #pragma unroll
            for (int q = 0; q < 2; ++q) {
                int ncn = ncp + 2 + q;
                uint32_t b = (uint32_t)(ncn & 3);
                const char* s1c = (const char*)g_w1 + ncn * 6656;
                const char* s2c = (const char*)g_w2 + ncn * 7680;
                for (int i = tid; i < 416; i += 256) cp16(smem_u + PB_W1 + b * 6656 + i * 16, s1c + i * 16);
                for (int i = tid; i < 480; i += 256) cp16(smem_u + PB_W2 + b * 7680 + i * 16, s2c + i * 16);
            }
            CP_COMMIT();
        }

        #pragma unroll
        for (int sub = 0; sub < 2; ++sub) {
            const int nc = ncp + sub;
            const uint32_t bW1_u = smem_u + PB_W1 + (uint32_t)((nc & 3) * 6656) + bW1rel;
            const uint32_t bW2_u = smem_u + PB_W2 + (uint32_t)((nc & 3) * 7680) + bW2rel;

            // GEMM1: A from xp regs
            float d1[4][4];
            #pragma unroll
            for (int i = 0; i < 4; ++i)
                #pragma unroll
                for (int j = 0; j < 4; ++j) d1[i][j] = 0.f;
            #pragma unroll
            for (int kt = 0; kt < 6; ++kt) {
                uint32_t a0 = xp[2 * kt][0], a1 = xp[2 * kt][1];
                uint32_t a2 = xp[2 * kt + 1][0], a3 = xp[2 * kt + 1][1];
                #pragma unroll
                for (int p = 0; p < 2; ++p) {
                    uint32_t b0, b1r, b2, b3;
                    ldm_x4(b0, b1r, b2, b3, bW1_u + p * 3328 + kt * 32);
                    mma_bf16(d1[2 * p],     a0, a1, a2, a3, b0, b1r);
                    mma_bf16(d1[2 * p + 1], a0, a1, a2, a3, b2, b3);
                }
            }
            // bias + GELU -> A-frags in regs
            uint32_t hp[4][2];
            #pragma unroll
            for (int nt = 0; nt < 4; ++nt) {
                int c = nt * 8 + 2 * t;
                float bb0 = sB1[nc * 32 + c], bb1 = sB1[nc * 32 + c + 1];
                hp[nt][0] = pack_bf16(gelu_fast(d1[nt][0] + bb0), gelu_fast(d1[nt][1] + bb1));
                hp[nt][1] = pack_bf16(gelu_fast(d1[nt][2] + bb0), gelu_fast(d1[nt][3] + bb1));
            }
            // GEMM2: A from hp regs
            #pragma unroll
            for (int kt = 0; kt < 2; ++kt) {
                uint32_t a0 = hp[2 * kt][0], a1 = hp[2 * kt][1];
                uint32_t a2 = hp[2 * kt + 1][0], a3 = hp[2 * kt + 1][1];
                #pragma unroll
                for (int p = 0; p < 6; ++p) {
                    uint32_t b0, b1r, b2, b3;
                    ldm_x4(b0, b1r, b2, b3, bW2_u + p * 1280 + kt * 32);
                    mma_bf16(d2[2 * p],     a0, a1, a2, a3, b0, b1r);
                    mma_bf16(d2[2 * p + 1], a0, a1, a2, a3, b2, b3);
                }
            }
        }
    }

    // ---- final: out = d2 + b2 + x1 (sX1 own rows), scatter ----
    {
        float* po0 = out + (size_t)src0 * 96;
        float* po1 = out + (size_t)src1 * 96;
        #pragma unroll
        for (int nt = 0; nt < 12; ++nt) {
            int c = nt * 8 + 2 * t;
            float bb0 = sB2[c], bb1 = sB2[c + 1];
            float2 xa = *(const float2*)(sX1 + rowA * 98 + c);
            float2 xb = *(const float2*)(sX1 + (rowA + 8) * 98 + c);
            float2 r1, r2;
            r1.x = d2[nt][0] + bb0 + xa.x;  r1.y = d2[nt][1] + bb1 + xa.y;
            r2.x = d2[nt][2] + bb0 + xb.x;  r2.y = d2[nt][3] + bb1 + xb.y;
            *(float2*)(po0 + c) = r1;
            *(float2*)(po1 + c) = r2;
        }
    }
}

extern "C" void kernel_launch(void* const* d_in, const int* in_sizes, int n_in,
                              void* d_out, int out_size)
{
    const float* x    = (const float*)d_in[0];
    const float* n1w  = (const float*)d_in[1];
    const float* n1b  = (const float*)d_in[2];
    const float* qkvw = (const float*)d_in[3];
    const float* qkvb = (const float*)d_in[4];
    const float* rpb  = (const float*)d_in[5];
    const float* pw   = (const float*)d_in[6];
    const float* pb   = (const float*)d_in[7];
    const float* n2w  = (const float*)d_in[8];
    const float* n2b  = (const float*)d_in[9];
    const float* w1   = (const float*)d_in[10];
    const float* b1   = (const float*)d_in[11];
    const float* w2   = (const float*)d_in[12];
    const float* b2   = (const float*)d_in[13];
    float* out = (float*)d_out;

    cudaFuncSetAttribute(block_kernel, cudaFuncAttributeMaxDynamicSharedMemorySize, SM_BYTES);

    prep_kernel<<<64, 256>>>(qkvw, pw, w1, w2);
    block_kernel<<<2048, 256, SM_BYTES>>>(x, n1w, n1b, qkvb, rpb, pb, n2w, n2b, b1, b2, out);
}

// round 17
// speedup vs baseline: 1.0723x; 1.0183x over previous
#include <cuda_runtime.h>
#include <cuda_bf16.h>
#include <math.h>
#include <stdint.h>

// pre-converted bf16 weights in smem-ready layouts (written by prep_kernel each launch)
static __device__ __align__(16) __nv_bfloat16 g_wqkv[3 * 96 * 104];  // [h][n][k], stride 104
static __device__ __align__(16) __nv_bfloat16 g_wproj[96 * 104];     // [n][k]
static __device__ __align__(16) __nv_bfloat16 g_w1[12 * 32 * 104];   // [nc][n][k]
static __device__ __align__(16) __nv_bfloat16 g_w2[12 * 96 * 40];    // [nc][n][k]

__global__ void prep_kernel(
    const float* __restrict__ qkvw, const float* __restrict__ pw,
    const float* __restrict__ w1,   const float* __restrict__ w2)
{
    const int stride = gridDim.x * blockDim.x;
    const int tid0 = blockIdx.x * blockDim.x + threadIdx.x;
    for (int i = tid0; i < 3 * 96 * 96; i += stride) {
        int h = i / 9216, r = i - h * 9216, n = r / 96, k = r - n * 96;
        int sec = n >> 5, d = n & 31;
        g_wqkv[h * 9984 + n * 104 + k] = __float2bfloat16(qkvw[k * 288 + sec * 96 + h * 32 + d]);
    }
    for (int i = tid0; i < 96 * 96; i += stride) {
        int n = i / 96, k = i - n * 96;
        g_wproj[n * 104 + k] = __float2bfloat16(pw[k * 96 + n]);
    }
    for (int i = tid0; i < 96 * 384; i += stride) {
        int k = i / 384, c = i - k * 384;
        int nc = c >> 5, n = c & 31;
        g_w1[nc * 3328 + n * 104 + k] = __float2bfloat16(w1[i]);
    }
    for (int i = tid0; i < 384 * 96; i += stride) {
        int kr = i / 96, n = i - kr * 96;
        int nc = kr >> 5, kk = kr & 31;
        g_w2[nc * 3840 + n * 40 + kk] = __float2bfloat16(w2[i]);
    }
}

// ===================== mma / ldmatrix / cp.async helpers =====================
__device__ __forceinline__ void mma_bf16(float d[4],
    uint32_t a0, uint32_t a1, uint32_t a2, uint32_t a3, uint32_t b0, uint32_t b1)
{
    asm volatile(
        "mma.sync.aligned.m16n8k16.row.col.f32.bf16.bf16.f32 "
        "{%0,%1,%2,%3},{%4,%5,%6,%7},{%8,%9},{%0,%1,%2,%3};"
        : "+f"(d[0]), "+f"(d[1]), "+f"(d[2]), "+f"(d[3])
        : "r"(a0), "r"(a1), "r"(a2), "r"(a3), "r"(b0), "r"(b1));
}
__device__ __forceinline__ void ldm_x4(uint32_t& r0, uint32_t& r1, uint32_t& r2, uint32_t& r3,
                                       uint32_t addr)
{
    asm volatile("ldmatrix.sync.aligned.m8n8.x4.shared.b16 {%0,%1,%2,%3}, [%4];"
                 : "=r"(r0), "=r"(r1), "=r"(r2), "=r"(r3) : "r"(addr));
}
__device__ __forceinline__ void ldm_x4_trans(uint32_t& r0, uint32_t& r1, uint32_t& r2, uint32_t& r3,
                                             uint32_t addr)
{
    asm volatile("ldmatrix.sync.aligned.m8n8.x4.trans.shared.b16 {%0,%1,%2,%3}, [%4];"
                 : "=r"(r0), "=r"(r1), "=r"(r2), "=r"(r3) : "r"(addr));
}
__device__ __forceinline__ uint32_t pack_bf16(float lo, float hi) {
    uint32_t r;
    asm("cvt.rn.bf16x2.f32 %0, %1, %2;" : "=r"(r) : "f"(hi), "f"(lo)); // d.hi=%1, d.lo=%2
    return r;
}
__device__ __forceinline__ float gelu_fast(float v) {
    float u = v * (0.79788456f + 0.035677408f * v * v);
    float th; asm("tanh.approx.f32 %0, %1;" : "=f"(th) : "f"(u));
    return 0.5f * v * (1.f + th);
}
__device__ __forceinline__ void cp16(uint32_t dst, const void* src) {
    asm volatile("cp.async.cg.shared.global [%0], [%1], 16;" :: "r"(dst), "l"(src) : "memory");
}
#define CP_COMMIT() asm volatile("cp.async.commit_group;" ::: "memory")
#define CP_WAIT0()  asm volatile("cp.async.wait_group 0;" ::: "memory")
#define WIN_BAR(id) asm volatile("bar.sync %0, 128;" :: "r"(id) : "memory")

// ---------------- fused kernel smem layout (bytes) ----------------
// Phase A:
constexpr uint32_t AB_SA  = 0;        // 128 x 104 bf16 LN1 tokens      (26624)
constexpr uint32_t AB_SW0 = 26624;    // weight buf 0: 96 x 104 bf16    (19968)
constexpr uint32_t AB_SW1 = 46592;    // weight buf 1                   (19968) -> 66560
constexpr uint32_t AB_SK  = 66560;    // 128 x 40 bf16                  (10240) -> 76800
constexpr uint32_t AB_SV  = 76800;    // 128 x 40 bf16 (row-major V)    (10240) -> 87040
constexpr uint32_t AB_RPB = 87040;    // 675 f32                        -> 89744 (pad)
constexpr uint32_t AB_REG = 89744;    // 128 int                        -> 90256
constexpr uint32_t AB_BQ  = 90256;    // 288 f32 qkv bias (per-head)    -> 91408
// Phase B (overlays phase A up to 109440):
constexpr uint32_t PB_X1  = 0;        // x1 f32 128 x stride 98         (50176)
constexpr uint32_t PB_W1  = 50176;    // 4 x (32 x 104 bf16 = 6656)     -> 76800
constexpr uint32_t PB_W2  = 76800;    // 4 x (96 x 40 bf16 = 7680)      -> 107520
constexpr uint32_t PB_B1  = 107520;   // 384 f32 fc1 bias               -> 109056
constexpr uint32_t PB_B2  = 109056;   // 96 f32 fc2 bias                -> 109440
// Persistent (never overlaid):
constexpr uint32_t PS_SRC = 109440;   // 128 int                        -> 109952
constexpr uint32_t PS_BP  = 109952;   // 96 f32 proj bias               -> 110336
constexpr uint32_t PS_N2W = 110336;   // 96 f32                         -> 110720
constexpr uint32_t PS_N2B = 110720;   // 96 f32                         -> 111104
constexpr uint32_t SM_BYTES = 111104;

__global__ __launch_bounds__(256, 2) void block_kernel(
    const float* __restrict__ x,
    const float* __restrict__ n1w, const float* __restrict__ n1b,
    const float* __restrict__ qkvb,
    const float* __restrict__ rpb,
    const float* __restrict__ pb,
    const float* __restrict__ n2w, const float* __restrict__ n2b,
    const float* __restrict__ b1,  const float* __restrict__ b2,
    float* __restrict__ out)
{
    extern __shared__ char smc[];
    __nv_bfloat16* sA  = (__nv_bfloat16*)(smc + AB_SA);
    __nv_bfloat16* sK  = (__nv_bfloat16*)(smc + AB_SK);
    __nv_bfloat16* sV  = (__nv_bfloat16*)(smc + AB_SV);
    float* sRPB = (float*)(smc + AB_RPB);
    int*   sReg = (int*)(smc + AB_REG);
    int*   sSrc = (int*)(smc + PS_SRC);
    float* sBQ  = (float*)(smc + AB_BQ);
    float* sBP  = (float*)(smc + PS_BP);
    float* sN2W = (float*)(smc + PS_N2W);
    float* sN2B = (float*)(smc + PS_N2B);
    float* sX1  = (float*)(smc + PB_X1);
    float* sB1  = (float*)(smc + PB_B1);
    float* sB2  = (float*)(smc + PB_B2);

    const uint32_t smem_u = (uint32_t)__cvta_generic_to_shared(smc);

    const int tid  = threadIdx.x;
    const int w    = tid >> 5;
    const int lane = tid & 31;
    const int g    = lane >> 2;
    const int t    = lane & 3;
    const int rowA = w * 16 + g;

    // ldmatrix per-lane tile coords
    const int quad = lane >> 3, qr = lane & 7;
    const int arow = (quad & 1) * 8 + qr;
    const int acol = (quad >> 1) * 8;
    const int brow = (quad >> 1) * 8 + qr;
    const int bcol = (quad & 1) * 8;
    // trans-ldmatrix coords (for row-major V -> col-major B frags)
    const int vrow = (quad & 1) * 8 + qr;
    const int vcol = (quad >> 1) * 8;

    const int bw  = blockIdx.x;
    const int bb  = bw >> 7;
    const int wh  = (bw >> 3) & 15;
    const int wwp = bw & 7;
    const float scale = 0.17677669529663687f;

    // kick off head-0 weight staging immediately
    for (int i = tid; i < 1248; i += 256)
        cp16(smem_u + AB_SW0 + i * 16, (const char*)g_wqkv + i * 16);
    CP_COMMIT();

    // metadata + bias staging
    if (tid < 128) {
        int win0 = tid >> 6, tok = tid & 63;
        int i = tok >> 3, j = tok & 7;
        int hr = wh * 8 + i, wr = (wwp * 2 + win0) * 8 + j;
        int hs = (hr + 4) & 127, ws = (wr + 4) & 127;
        sSrc[tid] = bb * 16384 + hs * 128 + ws;
        int rh = hr < 120 ? 0 : (hr < 124 ? 1 : 2);
        int rw = wr < 120 ? 0 : (wr < 124 ? 1 : 2);
        sReg[tid] = rh * 3 + rw;
    }
    for (int q = tid; q < 675; q += 256) sRPB[q] = rpb[q];
    for (int i = tid; i < 288; i += 256) {
        int h = i / 96, n = i - h * 96;
        sBQ[i] = qkvb[(n >> 5) * 96 + h * 32 + (n & 31)];
    }
    if (tid < 96) { sBP[tid] = pb[tid]; sN2W[tid] = n2w[tid]; sN2B[tid] = n2b[tid]; }
    __syncthreads();

    // gather + LN1 -> sA bf16 (own-warp rows)
    {
        float wv0 = n1w[lane], wv1 = n1w[lane + 32], wv2 = n1w[lane + 64];
        float bv0 = n1b[lane], bv1 = n1b[lane + 32], bv2 = n1b[lane + 64];
        for (int rr = 0; rr < 16; ++rr) {
            int n = w * 16 + rr;
            const float* px = x + (size_t)sSrc[n] * 96;
            float v0 = px[lane], v1 = px[lane + 32], v2 = px[lane + 64];
            float s = v0 + v1 + v2, s2 = v0 * v0 + v1 * v1 + v2 * v2;
            #pragma unroll
            for (int o = 16; o; o >>= 1) {
                s  += __shfl_xor_sync(0xffffffffu, s, o);
                s2 += __shfl_xor_sync(0xffffffffu, s2, o);
            }
            float mu = s * (1.f / 96.f);
            float rs = rsqrtf(s2 * (1.f / 96.f) - mu * mu + 1e-5f);
            sA[n * 104 + lane]      = __float2bfloat16((v0 - mu) * rs * wv0 + bv0);
            sA[n * 104 + lane + 32] = __float2bfloat16((v1 - mu) * rs * wv1 + bv1);
            sA[n * 104 + lane + 64] = __float2bfloat16((v2 - mu) * rs * wv2 + bv2);
        }
    }

    const int win = w >> 2;
    const int wl  = w & 3;

    const uint32_t aA_u = smem_u + AB_SA + (uint32_t)(((w * 16 + arow) * 104 + acol) * 2);
    const uint32_t bWrel = (uint32_t)((brow * 104 + bcol) * 2);
    const uint32_t bK_u = smem_u + AB_SK + (uint32_t)(((win * 64 + brow) * 40 + bcol) * 2);
    const uint32_t bV_u = smem_u + AB_SV + (uint32_t)(((win * 64 + vrow) * 40 + vcol) * 2);
    const uint32_t bW1rel = (uint32_t)((brow * 104 + bcol) * 2);
    const uint32_t bW2rel = (uint32_t)((brow * 40 + bcol) * 2);

    // head-invariant softmax metadata: rows, and 16-bit region-equality masks
    const int tokr0 = wl * 16 + g, tokr1 = tokr0 + 8;
    const int iq0 = tokr0 >> 3, jq0 = tokr0 & 7;
    const int iq1 = tokr1 >> 3, jq1 = tokr1 & 7;
    uint32_t mask0 = 0, mask1 = 0;
    {
        int reg0 = sReg[win * 64 + tokr0], reg1 = sReg[win * 64 + tokr1];
        #pragma unroll
        for (int nt = 0; nt < 8; ++nt) {
            #pragma unroll
            for (int jj = 0; jj < 2; ++jj) {
                int m = nt * 8 + 2 * t + jj;
                int regm = sReg[win * 64 + m];
                int b = nt * 2 + jj;
                mask0 |= (uint32_t)(regm == reg0) << b;
                mask1 |= (uint32_t)(regm == reg1) << b;
            }
        }
    }

    float oacc[12][4];
    #pragma unroll
    for (int i = 0; i < 12; ++i)
        #pragma unroll
        for (int j = 0; j < 4; ++j) oacc[i][j] = 0.f;

    // =================== Phase A: attention ===================
    for (int h = 0; h < 3; ++h) {
        CP_WAIT0();
        __syncthreads();   // weights buf h&1 visible; prev head's K/V consumers done

        if (h < 2) {
            uint32_t dstb = smem_u + ((h & 1) ? AB_SW0 : AB_SW1);
            const char* srcb = (const char*)g_wqkv + (h + 1) * 19968;
            for (int i = tid; i < 1248; i += 256) cp16(dstb + i * 16, srcb + i * 16);
        } else {
            uint32_t dstb = smem_u + AB_SW1;
            const char* srcb = (const char*)g_wproj;
            for (int i = tid; i < 1248; i += 256) cp16(dstb + i * 16, srcb + i * 16);
        }
        CP_COMMIT();

        const uint32_t bW_u = smem_u + ((h & 1) ? AB_SW1 : AB_SW0) + bWrel;

        // ---- QKV GEMM: d(16 x 96) ----
        float d[12][4];
        #pragma unroll
        for (int i = 0; i < 12; ++i)
            #pragma unroll
            for (int j = 0; j < 4; ++j) d[i][j] = 0.f;
        #pragma unroll
        for (int kt = 0; kt < 6; ++kt) {
            uint32_t a0, a1, a2, a3;
            ldm_x4(a0, a1, a2, a3, aA_u + kt * 32);
            #pragma unroll
            for (int p = 0; p < 6; ++p) {
                uint32_t b0, b1r, b2, b3;
                ldm_x4(b0, b1r, b2, b3, bW_u + p * 3328 + kt * 32);
                mma_bf16(d[2 * p],     a0, a1, a2, a3, b0, b1r);
                mma_bf16(d[2 * p + 1], a0, a1, a2, a3, b2, b3);
            }
        }
        // epilogue: Q -> regs (scaled), K -> smem, V -> smem (row-major)
        uint32_t qp[4][2];
        #pragma unroll
        for (int nt = 0; nt < 12; ++nt) {
            int c = nt * 8 + 2 * t;
            float bb0 = sBQ[h * 96 + c], bb1 = sBQ[h * 96 + c + 1];
            float v0 = d[nt][0] + bb0, v1 = d[nt][1] + bb1;
            float v2 = d[nt][2] + bb0, v3 = d[nt][3] + bb1;
            if (nt < 4) {
                qp[nt][0] = pack_bf16(v0 * scale, v1 * scale);
                qp[nt][1] = pack_bf16(v2 * scale, v3 * scale);
            } else if (nt < 8) {
                int dim = c - 32;
                *(uint32_t*)(sK + rowA * 40       + dim) = pack_bf16(v0, v1);
                *(uint32_t*)(sK + (rowA + 8) * 40 + dim) = pack_bf16(v2, v3);
            } else {
                int dim = c - 64;
                *(uint32_t*)(sV + rowA * 40       + dim) = pack_bf16(v0, v1);
                *(uint32_t*)(sV + (rowA + 8) * 40 + dim) = pack_bf16(v2, v3);
            }
        }
        WIN_BAR(1 + win);   // publish K / V within this window only

        // ---- scores: S(16 x 64) = Q @ K^T ----
        float d1[8][4];
        #pragma unroll
        for (int i = 0; i < 8; ++i)
            #pragma unroll
            for (int j = 0; j < 4; ++j) d1[i][j] = 0.f;
        #pragma unroll
        for (int kt = 0; kt < 2; ++kt) {
            uint32_t a0 = qp[2 * kt][0], a1 = qp[2 * kt][1];
            uint32_t a2 = qp[2 * kt + 1][0], a3 = qp[2 * kt + 1][1];
            #pragma unroll
            for (int p = 0; p < 4; ++p) {
                uint32_t b0, b1r, b2, b3;
                ldm_x4(b0, b1r, b2, b3, bK_u + p * 1280 + kt * 32);
                mma_bf16(d1[2 * p],     a0, a1, a2, a3, b0, b1r);
                mma_bf16(d1[2 * p + 1], a0, a1, a2, a3, b2, b3);
            }
        }
        // rel-pos bias + shift mask + softmax
        {
            #pragma unroll
            for (int nt = 0; nt < 8; ++nt) {
                #pragma unroll
                for (int jj = 0; jj < 2; ++jj) {
                    int m = nt * 8 + 2 * t + jj;
                    int im = m >> 3, jm = m & 7;
                    int b = nt * 2 + jj;
                    d1[nt][jj]     += sRPB[((iq0 - im + 7) * 15 + (jq0 - jm + 7)) * 3 + h]
                                      + (((mask0 >> b) & 1u) ? 0.f : -100.f);
                    d1[nt][2 + jj] += sRPB[((iq1 - im + 7) * 15 + (jq1 - jm + 7)) * 3 + h]
                                      + (((mask1 >> b) & 1u) ? 0.f : -100.f);
                }
            }
            float mx0 = -1e30f, mx1 = -1e30f;
            #pragma unroll
            for (int nt = 0; nt < 8; ++nt) {
                mx0 = fmaxf(mx0, fmaxf(d1[nt][0], d1[nt][1]));
                mx1 = fmaxf(mx1, fmaxf(d1[nt][2], d1[nt][3]));
            }
            #pragma unroll
            for (int o = 1; o <= 2; o <<= 1) {
                mx0 = fmaxf(mx0, __shfl_xor_sync(0xffffffffu, mx0, o));
                mx1 = fmaxf(mx1, __shfl_xor_sync(0xffffffffu, mx1, o));
            }
            float sum0 = 0.f, sum1 = 0.f;
            #pragma unroll
            for (int nt = 0; nt < 8; ++nt) {
                d1[nt][0] = __expf(d1[nt][0] - mx0); sum0 += d1[nt][0];
                d1[nt][1] = __expf(d1[nt][1] - mx0); sum0 += d1[nt][1];
                d1[nt][2] = __expf(d1[nt][2] - mx1); sum1 += d1[nt][2];
                d1[nt][3] = __expf(d1[nt][3] - mx1); sum1 += d1[nt][3];
            }
            #pragma unroll
            for (int o = 1; o <= 2; o <<= 1) {
                sum0 += __shfl_xor_sync(0xffffffffu, sum0, o);
                sum1 += __shfl_xor_sync(0xffffffffu, sum1, o);
            }
            float inv0 = 1.f / sum0, inv1 = 1.f / sum1;
            uint32_t pp[8][2];
            #pragma unroll
            for (int nt = 0; nt < 8; ++nt) {
                pp[nt][0] = pack_bf16(d1[nt][0] * inv0, d1[nt][1] * inv0);
                pp[nt][1] = pack_bf16(d1[nt][2] * inv1, d1[nt][3] * inv1);
            }
            // ---- PV: B-frags via trans-ldmatrix from row-major V ----
            #pragma unroll
            for (int kt = 0; kt < 4; ++kt) {
                uint32_t a0 = pp[2 * kt][0], a1 = pp[2 * kt][1];
                uint32_t a2 = pp[2 * kt + 1][0], a3 = pp[2 * kt + 1][1];
                #pragma unroll
                for (int p = 0; p < 2; ++p) {
                    uint32_t b0, b1r, b2, b3;
                    ldm_x4_trans(b0, b1r, b2, b3, bV_u + kt * 1280 + p * 32);
                    mma_bf16(oacc[h * 4 + 2 * p],     a0, a1, a2, a3, b0, b1r);
                    mma_bf16(oacc[h * 4 + 2 * p + 1], a0, a1, a2, a3, b2, b3);
                }
            }
        }
    }

    // ---- proj: A-frags from oacc regs, weights in buf1 ----
    CP_WAIT0();
    __syncthreads();
    const int src0 = sSrc[rowA], src1 = sSrc[rowA + 8];
    uint32_t op[12][2];
    #pragma unroll
    for (int nt = 0; nt < 12; ++nt) {
        op[nt][0] = pack_bf16(oacc[nt][0], oacc[nt][1]);
        op[nt][1] = pack_bf16(oacc[nt][2], oacc[nt][3]);
    }
    float dproj[12][4];
    #pragma unroll
    for (int i = 0; i < 12; ++i)
        #pragma unroll
        for (int j = 0; j < 4; ++j) dproj[i][j] = 0.f;
    {
        const uint32_t bWp_u = smem_u + AB_SW1 + bWrel;
        #pragma unroll
        for (int kt = 0; kt < 6; ++kt) {
            uint32_t a0 = op[2 * kt][0], a1 = op[2 * kt][1];
            uint32_t a2 = op[2 * kt + 1][0], a3 = op[2 * kt + 1][1];
            #pragma unroll
            for (int p = 0; p < 6; ++p) {
                uint32_t b0, b1r, b2, b3;
                ldm_x4(b0, b1r, b2, b3, bWp_u + p * 3328 + kt * 32);
                mma_bf16(dproj[2 * p],     a0, a1, a2, a3, b0, b1r);
                mma_bf16(dproj[2 * p + 1], a0, a1, a2, a3, b2, b3);
            }
        }
    }
    __syncthreads();   // everyone done with phase-A smem before overlay

    // =================== Phase B: x1 + LN2 + MLP (4 buffers, 2 chunks per barrier) ===================
    // prefetch chunks 0 and 1 as ONE group
    for (int i = tid; i < 416; i += 256) cp16(smem_u + PB_W1 + i * 16, (const char*)g_w1 + i * 16);
    for (int i = tid; i < 480; i += 256) cp16(smem_u + PB_W2 + i * 16, (const char*)g_w2 + i * 16);
    for (int i = tid; i < 416; i += 256) cp16(smem_u + PB_W1 + 6656 + i * 16, (const char*)g_w1 + 6656 + i * 16);
    for (int i = tid; i < 480; i += 256) cp16(smem_u + PB_W2 + 7680 + i * 16, (const char*)g_w2 + 7680 + i * 16);
    CP_COMMIT();

    // x1 = proj + pb + x (regs + sX1 store); LN2 in regs -> xp A-frags
    uint32_t xp[12][2];
    {
        const float* px0 = x + (size_t)src0 * 96;
        const float* px1 = x + (size_t)src1 * 96;
        float x1v[12][4];
        float s0 = 0.f, q0 = 0.f, s1 = 0.f, q1 = 0.f;
        #pragma unroll
        for (int nt = 0; nt < 12; ++nt) {
            int c = nt * 8 + 2 * t;
            float bb0 = sBP[c], bb1 = sBP[c + 1];
            float2 xa = *(const float2*)(px0 + c);
            float2 xb = *(const float2*)(px1 + c);
            float v0 = dproj[nt][0] + bb0 + xa.x;
            float v1 = dproj[nt][1] + bb1 + xa.y;
            float v2 = dproj[nt][2] + bb0 + xb.x;
            float v3 = dproj[nt][3] + bb1 + xb.y;
            x1v[nt][0] = v0; x1v[nt][1] = v1; x1v[nt][2] = v2; x1v[nt][3] = v3;
            float2 r1; r1.x = v0; r1.y = v1;
            float2 r2; r2.x = v2; r2.y = v3;
            *(float2*)(sX1 + rowA * 98 + c)       = r1;
            *(float2*)(sX1 + (rowA + 8) * 98 + c) = r2;
            s0 += v0 + v1;  q0 += v0 * v0 + v1 * v1;
            s1 += v2 + v3;  q1 += v2 * v2 + v3 * v3;
        }
        #pragma unroll
        for (int o = 1; o <= 2; o <<= 1) {
            s0 += __shfl_xor_sync(0xffffffffu, s0, o);
            q0 += __shfl_xor_sync(0xffffffffu, q0, o);
            s1 += __shfl_xor_sync(0xffffffffu, s1, o);
            q1 += __shfl_xor_sync(0xffffffffu, q1, o);
        }
        float mu0 = s0 * (1.f / 96.f), mu1 = s1 * (1.f / 96.f);
        float rs0 = rsqrtf(q0 * (1.f / 96.f) - mu0 * mu0 + 1e-5f);
        float rs1 = rsqrtf(q1 * (1.f / 96.f) - mu1 * mu1 + 1e-5f);
        #pragma unroll
        for (int nt = 0; nt < 12; ++nt) {
            int c = nt * 8 + 2 * t;
            float w0v = sN2W[c], w1v = sN2W[c + 1];
            float b0v = sN2B[c], b1v = sN2B[c + 1];
            xp[nt][0] = pack_bf16((x1v[nt][0] - mu0) * rs0 * w0v + b0v,
                                  (x1v[nt][1] - mu0) * rs0 * w1v + b1v);
            xp[nt][1] = pack_bf16((x1v[nt][2] - mu1) * rs1 * w0v + b0v,
                                  (x1v[nt][3] - mu1) * rs1 * w1v + b1v);
        }
    }
    // stage fc biases
    for (int i = tid; i < 384; i += 256) sB1[i] = b1[i];
    if (tid < 96) sB2[tid] = b2[tid];

    float d2[12][4];
    #pragma unroll
    for (int i = 0; i < 12; ++i)
        #pragma unroll
        for (int j = 0; j < 4; ++j) d2[i][j] = 0.f;

    for (int ncp = 0; ncp < 12; ncp += 2) {
        CP_WAIT0();
        __syncthreads();   // chunks ncp, ncp+1 visible; buffers (ncp+2..3)&3 retired last iteration
        if (ncp + 2 < 12) {
            // prefetch chunks ncp+2, ncp+3 as one group
            #pragma unroll
            for (int q = 0; q < 2; ++q) {
                int ncn = ncp + 2 + q;
                uint32_t b = (uint32_t)(ncn & 3);
                const char* s1c = (const char*)g_w1 + ncn * 6656;
                const char* s2c = (const char*)g_w2 + ncn * 7680;
                for (int i = tid; i < 416; i += 256) cp16(smem_u + PB_W1 + b * 6656 + i * 16, s1c + i * 16);
                for (int i = tid; i < 480; i += 256) cp16(smem_u + PB_W2 + b * 7680 + i * 16, s2c + i * 16);
            }
            CP_COMMIT();
        }

        #pragma unroll
        for (int sub = 0; sub < 2; ++sub) {
            const int nc = ncp + sub;
            const uint32_t bW1_u = smem_u + PB_W1 + (uint32_t)((nc & 3) * 6656) + bW1rel;
            const uint32_t bW2_u = smem_u + PB_W2 + (uint32_t)((nc & 3) * 7680) + bW2rel;

            // GEMM1: A from xp regs
            float d1[4][4];
            #pragma unroll
            for (int i = 0; i < 4; ++i)
                #pragma unroll
                for (int j = 0; j < 4; ++j) d1[i][j] = 0.f;
            #pragma unroll
            for (int kt = 0; kt < 6; ++kt) {
                uint32_t a0 = xp[2 * kt][0], a1 = xp[2 * kt][1];
                uint32_t a2 = xp[2 * kt + 1][0], a3 = xp[2 * kt + 1][1];
                #pragma unroll
                for (int p = 0; p < 2; ++p) {
                    uint32_t b0, b1r, b2, b3;
                    ldm_x4(b0, b1r, b2, b3, bW1_u + p * 3328 + kt * 32);
                    mma_bf16(d1[2 * p],     a0, a1, a2, a3, b0, b1r);
                    mma_bf16(d1[2 * p + 1], a0, a1, a2, a3, b2, b3);
                }
            }
            // bias + GELU -> A-frags in regs
            uint32_t hp[4][2];
            #pragma unroll
            for (int nt = 0; nt < 4; ++nt) {
                int c = nt * 8 + 2 * t;
                float bb0 = sB1[nc * 32 + c], bb1 = sB1[nc * 32 + c + 1];
                hp[nt][0] = pack_bf16(gelu_fast(d1[nt][0] + bb0), gelu_fast(d1[nt][1] + bb1));
                hp[nt][1] = pack_bf16(gelu_fast(d1[nt][2] + bb0), gelu_fast(d1[nt][3] + bb1));
            }
            // GEMM2: A from hp regs
            #pragma unroll
            for (int kt = 0; kt < 2; ++kt) {
                uint32_t a0 = hp[2 * kt][0], a1 = hp[2 * kt][1];
                uint32_t a2 = hp[2 * kt + 1][0], a3 = hp[2 * kt + 1][1];
                #pragma unroll
                for (int p = 0; p < 6; ++p) {
                    uint32_t b0, b1r, b2, b3;
                    ldm_x4(b0, b1r, b2, b3, bW2_u + p * 1280 + kt * 32);
                    mma_bf16(d2[2 * p],     a0, a1, a2, a3, b0, b1r);
                    mma_bf16(d2[2 * p + 1], a0, a1, a2, a3, b2, b3);
                }
            }
        }
    }

    // ---- final: out = d2 + b2 + x1 (sX1 own rows), scatter ----
    {
        float* po0 = out + (size_t)src0 * 96;
        float* po1 = out + (size_t)src1 * 96;
        #pragma unroll
        for (int nt = 0; nt < 12; ++nt) {
            int c = nt * 8 + 2 * t;
            float bb0 = sB2[c], bb1 = sB2[c + 1];
            float2 xa = *(const float2*)(sX1 + rowA * 98 + c);
            float2 xb = *(const float2*)(sX1 + (rowA + 8) * 98 + c);
            float2 r1, r2;
            r1.x = d2[nt][0] + bb0 + xa.x;  r1.y = d2[nt][1] + bb1 + xa.y;
            r2.x = d2[nt][2] + bb0 + xb.x;  r2.y = d2[nt][3] + bb1 + xb.y;
            *(float2*)(po0 + c) = r1;
            *(float2*)(po1 + c) = r2;
        }
    }
}

extern "C" void kernel_launch(void* const* d_in, const int* in_sizes, int n_in,
                              void* d_out, int out_size)
{
    const float* x    = (const float*)d_in[0];
    const float* n1w  = (const float*)d_in[1];
    const float* n1b  = (const float*)d_in[2];
    const float* qkvw = (const float*)d_in[3];
    const float* qkvb = (const float*)d_in[4];
    const float* rpb  = (const float*)d_in[5];
    const float* pw   = (const float*)d_in[6];
    const float* pb   = (const float*)d_in[7];
    const float* n2w  = (const float*)d_in[8];
    const float* n2b  = (const float*)d_in[9];
    const float* w1   = (const float*)d_in[10];
    const float* b1   = (const float*)d_in[11];
    const float* w2   = (const float*)d_in[12];
    const float* b2   = (const float*)d_in[13];
    float* out = (float*)d_out;

    cudaFuncSetAttribute(block_kernel, cudaFuncAttributeMaxDynamicSharedMemorySize, SM_BYTES);

    prep_kernel<<<512, 256>>>(qkvw, pw, w1, w2);
    block_kernel<<<2048, 256, SM_BYTES>>>(x, n1w, n1b, qkvb, rpb, pb, n2w, n2b, b1, b2, out);
}